// round 11
// baseline (speedup 1.0000x reference)
#include <cuda_runtime.h>
#include <cstdint>
#include <cstddef>

// BioConvolution: 256 independent GEMMs  C_l[64,128] = A_l[64,1024] * B_l[1024,128]
//   A_l[m][k] = X[m, r*4+i, c*4+j, ch]  (k = i*256+j*64+ch, l = r*16+c)
//   B_l[k][f] = filters[l*131072 + k*128 + f]
//   out[(m*256+l)*128+f] = relu(C + bias[f])
//
// Round 11: the residual vs the HBM floor is exposed LDG latency (issue ->
// consume distance of one compute section). Fix: K-chunks of 32 with THREE
// rotating register buffers -> LDG(t+4) issued at iter t, consumed at iter
// t+2 (two compute sections + two syncs of cover). 4-stage f16 smem ring.
// Verified fp16 ldmatrix/mma math unchanged.

namespace {

constexpr int NST = 32;            // K chunks of 32
constexpr int AH  = 40;            // A smem stride (halves) = 80B
constexpr int BH  = 136;           // B smem stride (halves) = 272B
constexpr int TA_B  = 64 * AH * 2;           // 5120 B
constexpr int STG_B = TA_B + 32 * BH * 2;    // 13824 B per stage
constexpr int SMEM_BYTES = 4 * STG_B;        // 55296 B -> 2 CTAs/SM

__device__ __forceinline__ uint32_t smem_u32(const void* p) {
    return static_cast<uint32_t>(__cvta_generic_to_shared(p));
}
__device__ __forceinline__ uint32_t pack_h2(float lo, float hi) {
    uint32_t d;
    asm("cvt.rn.f16x2.f32 %0, %1, %2;" : "=r"(d) : "f"(hi), "f"(lo));
    return d;
}
__device__ __forceinline__ void sts64(uint32_t a, uint32_t x, uint32_t y) {
    asm volatile("st.shared.v2.b32 [%0], {%1,%2};" :: "r"(a), "r"(x), "r"(y));
}
__device__ __forceinline__ void ldmx4(uint32_t* r, uint32_t a) {
    asm volatile("ldmatrix.sync.aligned.m8n8.x4.shared.b16 {%0,%1,%2,%3}, [%4];"
                 : "=r"(r[0]), "=r"(r[1]), "=r"(r[2]), "=r"(r[3]) : "r"(a));
}
__device__ __forceinline__ void ldmx4t(uint32_t* r, uint32_t a) {
    asm volatile("ldmatrix.sync.aligned.m8n8.x4.trans.shared.b16 {%0,%1,%2,%3}, [%4];"
                 : "=r"(r[0]), "=r"(r[1]), "=r"(r[2]), "=r"(r[3]) : "r"(a));
}
__device__ __forceinline__ void mma_f16(float* c, const uint32_t* a, const uint32_t* b) {
    asm volatile(
        "mma.sync.aligned.m16n8k16.row.col.f32.f16.f16.f32 "
        "{%0,%1,%2,%3}, {%4,%5,%6,%7}, {%8,%9}, {%0,%1,%2,%3};"
        : "+f"(c[0]), "+f"(c[1]), "+f"(c[2]), "+f"(c[3])
        : "r"(a[0]), "r"(a[1]), "r"(a[2]), "r"(a[3]), "r"(b[0]), "r"(b[1]));
}

__global__ __launch_bounds__(256, 2)
void bioconv_d2_kernel(const float* __restrict__ X,
                       const float* __restrict__ filt,
                       const float* __restrict__ bias,
                       float* __restrict__ out) {
    extern __shared__ __align__(16) char smem[];
    const uint32_t sb = smem_u32(smem);

    const int tid = threadIdx.x;
    const int l   = blockIdx.x;
    const int r   = l >> 4;
    const int cc  = l & 15;

    // ---- coalesced loader mapping (chunk = 32 floats of K) ----
    const int ar = tid >> 3, ac = tid & 7;    // A f4: row v*32+ar, col ac (v 0..1)
    const int br = tid >> 5, bc = tid & 31;   // B f4: row v*8+br,  col bc (v 0..3)

    const float* gA0 = X + (size_t)ar * 262144 + r * 16384 + cc * 256 + ac * 4;
    const float* gB0 = filt + (size_t)l * 131072 + (size_t)br * 128 + bc * 4;

    const uint32_t a_sts = (uint32_t)(ar * AH + ac * 4) * 2;
    const uint32_t b_sts = (uint32_t)TA_B + (uint32_t)(br * BH + bc * 4) * 2;

    // ---- compute mapping: 8 warps, 2(M) x 4(N), warp tile 32x32 ----
    const int lane = tid & 31;
    const int wid  = tid >> 5;
    const int wm   = wid >> 2;
    const int wn   = wid & 3;
    const int g    = lane >> 2;
    const int t4   = lane & 3;

    const uint32_t a_off = (uint32_t)((wm * 32 + (lane & 15)) * 80 + (lane >> 4) * 16);
    const uint32_t b_off = (uint32_t)TA_B +
        (uint32_t)((lane & 15) * 272 + (wn * 32 + ((lane >> 4) & 1) * 8) * 2);

    float acc[2][4][4];
#pragma unroll
    for (int i = 0; i < 2; ++i)
#pragma unroll
        for (int j = 0; j < 4; ++j)
#pragma unroll
            for (int k = 0; k < 4; ++k) acc[i][j][k] = 0.f;

    float4 fb[3][6];  // 3 rotating chunk buffers: 2 A-f4 + 4 B-f4 each

    auto ldg_chunk = [&](int t, int b) {
        const float* ga = gA0 + (t >> 3) * 4096 + ((t >> 1) & 3) * 64 + (t & 1) * 32;
#pragma unroll
        for (int v = 0; v < 2; ++v)
            fb[b][v] = *reinterpret_cast<const float4*>(ga + (size_t)v * 32 * 262144);
        const float* gb = gB0 + (size_t)t * 4096;
#pragma unroll
        for (int v = 0; v < 4; ++v)
            fb[b][2 + v] = *reinterpret_cast<const float4*>(gb + v * 1024);
    };
    auto cvt_sts = [&](int s, int b) {
        const uint32_t base = sb + s * STG_B;
#pragma unroll
        for (int v = 0; v < 2; ++v)
            sts64(base + a_sts + v * 32 * (AH * 2),
                  pack_h2(fb[b][v].x, fb[b][v].y), pack_h2(fb[b][v].z, fb[b][v].w));
#pragma unroll
        for (int v = 0; v < 4; ++v)
            sts64(base + b_sts + v * 8 * (BH * 2),
                  pack_h2(fb[b][2 + v].x, fb[b][2 + v].y),
                  pack_h2(fb[b][2 + v].z, fb[b][2 + v].w));
    };

    // prologue: chunks 0,1 in smem; chunks 2,3 in fb[2],fb[0]
    ldg_chunk(0, 0); cvt_sts(0, 0);
    ldg_chunk(1, 1); cvt_sts(1, 1);
    ldg_chunk(2, 2);
    ldg_chunk(3, 0);

    for (int t = 0; t < NST; ++t) {
        __syncthreads();   // stage (t+2)%4 free; stage t%4 visible
        if (t + 2 < NST) cvt_sts((t + 2) & 3, (t + 2) % 3);
        if (t + 4 < NST) ldg_chunk(t + 4, (t + 4) % 3);  // consumed at iter t+2

        const uint32_t base = sb + (t & 3) * STG_B;
        const uint32_t aa = base + a_off;
        const uint32_t bb = base + b_off;

#pragma unroll
        for (int kh = 0; kh < 2; ++kh) {
            uint32_t A0[4], A1[4], B0[4], B1[4];
            ldmx4(A0, aa + kh * 32);
            ldmx4(A1, aa + 1280 + kh * 32);      // +16 rows * 80B
            ldmx4t(B0, bb + kh * 4352);          // +16 k-rows * 272B
            ldmx4t(B1, bb + 32 + kh * 4352);     // +16 n

            mma_f16(acc[0][0], A0, &B0[0]);
            mma_f16(acc[0][1], A0, &B0[2]);
            mma_f16(acc[0][2], A0, &B1[0]);
            mma_f16(acc[0][3], A0, &B1[2]);
            mma_f16(acc[1][0], A1, &B0[0]);
            mma_f16(acc[1][1], A1, &B0[2]);
            mma_f16(acc[1][2], A1, &B1[0]);
            mma_f16(acc[1][3], A1, &B1[2]);
        }
    }

    // ---- epilogue: bias + relu (verified) ----
#pragma unroll
    for (int nt = 0; nt < 4; ++nt) {
        const int n0 = wn * 32 + nt * 8 + t4 * 2;
        const float2 bv = *reinterpret_cast<const float2*>(bias + n0);
#pragma unroll
        for (int mt = 0; mt < 2; ++mt) {
            const int m = wm * 32 + mt * 16 + g;
            float2 o0, o1;
            o0.x = fmaxf(acc[mt][nt][0] + bv.x, 0.f);
            o0.y = fmaxf(acc[mt][nt][1] + bv.y, 0.f);
            o1.x = fmaxf(acc[mt][nt][2] + bv.x, 0.f);
            o1.y = fmaxf(acc[mt][nt][3] + bv.y, 0.f);
            *reinterpret_cast<float2*>(out + ((size_t)m * 256 + l) * 128 + n0) = o0;
            *reinterpret_cast<float2*>(out + ((size_t)(m + 8) * 256 + l) * 128 + n0) = o1;
        }
    }
}

}  // namespace

extern "C" void kernel_launch(void* const* d_in, const int* in_sizes, int n_in,
                              void* d_out, int out_size) {
    const float* X    = (const float*)d_in[0];
    const float* filt = (const float*)d_in[1];
    const float* bias = (const float*)d_in[2];
    float* out        = (float*)d_out;

    cudaFuncSetAttribute(bioconv_d2_kernel,
                         cudaFuncAttributeMaxDynamicSharedMemorySize, SMEM_BYTES);
    bioconv_d2_kernel<<<256, 256, SMEM_BYTES>>>(X, filt, bias, out);
}

// round 12
// speedup vs baseline: 1.5972x; 1.5972x over previous
#include <cuda_runtime.h>
#include <cstdint>
#include <cstddef>

// BioConvolution: 256 independent GEMMs  C_l[64,128] = A_l[64,1024] * B_l[1024,128]
//   A_l[m][k] = X[m, r*4+i, c*4+j, ch]  (k = i*256+j*64+ch, l = r*16+c)
//   B_l[k][f] = filters[l*131072 + k*128 + f]
//   out[(m*256+l)*128+f] = relu(C + bias[f])
//
// Round 12: distance-2 LDG retest with STATIC register buffers. Round 11's
// fb[3][6] with runtime index was demoted to local memory (the regression was
// implementation, not theory). Two named Buf structs + loop unrolled x2 keep
// everything in registers: LDG(t+4) issued at iter t, consumed at iter t+2 --
// two compute sections + two syncs of latency cover. 4-stage f16 ring,
// chunk = 32 K-floats, verified fp16 ldmatrix/mma math unchanged.

namespace {

constexpr int NST = 32;            // K chunks of 32
constexpr int AH  = 40;            // A smem stride (halves) = 80B
constexpr int BH  = 136;           // B smem stride (halves) = 272B
constexpr int TA_B  = 64 * AH * 2;           // 5120 B
constexpr int STG_B = TA_B + 32 * BH * 2;    // 13824 B per stage
constexpr int SMEM_BYTES = 4 * STG_B;        // 55296 B -> 2 CTAs/SM

__device__ __forceinline__ uint32_t smem_u32(const void* p) {
    return static_cast<uint32_t>(__cvta_generic_to_shared(p));
}
__device__ __forceinline__ uint32_t pack_h2(float lo, float hi) {
    uint32_t d;
    asm("cvt.rn.f16x2.f32 %0, %1, %2;" : "=r"(d) : "f"(hi), "f"(lo));
    return d;
}
__device__ __forceinline__ void sts64(uint32_t a, uint32_t x, uint32_t y) {
    asm volatile("st.shared.v2.b32 [%0], {%1,%2};" :: "r"(a), "r"(x), "r"(y));
}
__device__ __forceinline__ void ldmx4(uint32_t* r, uint32_t a) {
    asm volatile("ldmatrix.sync.aligned.m8n8.x4.shared.b16 {%0,%1,%2,%3}, [%4];"
                 : "=r"(r[0]), "=r"(r[1]), "=r"(r[2]), "=r"(r[3]) : "r"(a));
}
__device__ __forceinline__ void ldmx4t(uint32_t* r, uint32_t a) {
    asm volatile("ldmatrix.sync.aligned.m8n8.x4.trans.shared.b16 {%0,%1,%2,%3}, [%4];"
                 : "=r"(r[0]), "=r"(r[1]), "=r"(r[2]), "=r"(r[3]) : "r"(a));
}
__device__ __forceinline__ void mma_f16(float* c, const uint32_t* a, const uint32_t* b) {
    asm volatile(
        "mma.sync.aligned.m16n8k16.row.col.f32.f16.f16.f32 "
        "{%0,%1,%2,%3}, {%4,%5,%6,%7}, {%8,%9}, {%0,%1,%2,%3};"
        : "+f"(c[0]), "+f"(c[1]), "+f"(c[2]), "+f"(c[3])
        : "r"(a[0]), "r"(a[1]), "r"(a[2]), "r"(a[3]), "r"(b[0]), "r"(b[1]));
}

struct Buf { float4 a0, a1, b0, b1, b2, b3; };  // one 32-K chunk per thread

__global__ __launch_bounds__(256, 2)
void bioconv_d2s_kernel(const float* __restrict__ X,
                        const float* __restrict__ filt,
                        const float* __restrict__ bias,
                        float* __restrict__ out) {
    extern __shared__ __align__(16) char smem[];
    const uint32_t sb = smem_u32(smem);

    const int tid = threadIdx.x;
    const int l   = blockIdx.x;
    const int r   = l >> 4;
    const int cc  = l & 15;

    // ---- coalesced loader mapping (chunk = 32 K-floats) ----
    const int ar = tid >> 3, ac = tid & 7;    // A f4: rows ar, ar+32; col ac
    const int br = tid >> 5, bc = tid & 31;   // B f4: rows v*8+br; col bc

    const float* gA0 = X + (size_t)ar * 262144 + r * 16384 + cc * 256 + ac * 4;
    const float* gB0 = filt + (size_t)l * 131072 + (size_t)br * 128 + bc * 4;

    const uint32_t a_sts = (uint32_t)(ar * AH + ac * 4) * 2;
    const uint32_t b_sts = (uint32_t)TA_B + (uint32_t)(br * BH + bc * 4) * 2;

    // ---- compute mapping: 8 warps, 2(M) x 4(N), warp tile 32x32 (verified) ----
    const int lane = tid & 31;
    const int wid  = tid >> 5;
    const int wm   = wid >> 2;
    const int wn   = wid & 3;
    const int g    = lane >> 2;
    const int t4   = lane & 3;

    const uint32_t a_off = (uint32_t)((wm * 32 + (lane & 15)) * 80 + (lane >> 4) * 16);
    const uint32_t b_off = (uint32_t)TA_B +
        (uint32_t)((lane & 15) * 272 + (wn * 32 + ((lane >> 4) & 1) * 8) * 2);

    float acc[2][4][4];
#pragma unroll
    for (int i = 0; i < 2; ++i)
#pragma unroll
        for (int j = 0; j < 4; ++j)
#pragma unroll
            for (int k = 0; k < 4; ++k) acc[i][j][k] = 0.f;

    Buf bA, bB;  // two static chunk buffers (no dynamic indexing)

    auto ldg_chunk = [&](Buf& b, int t) {
        const float* ga = gA0 + (t >> 3) * 4096 + ((t >> 1) & 3) * 64 + (t & 1) * 32;
        b.a0 = *reinterpret_cast<const float4*>(ga);
        b.a1 = *reinterpret_cast<const float4*>(ga + (size_t)32 * 262144);
        const float* gb = gB0 + (size_t)t * 4096;
        b.b0 = *reinterpret_cast<const float4*>(gb);
        b.b1 = *reinterpret_cast<const float4*>(gb + 1024);
        b.b2 = *reinterpret_cast<const float4*>(gb + 2048);
        b.b3 = *reinterpret_cast<const float4*>(gb + 3072);
    };
    auto cvt_sts = [&](int s, const Buf& b) {
        const uint32_t base = sb + s * STG_B;
        sts64(base + a_sts, pack_h2(b.a0.x, b.a0.y), pack_h2(b.a0.z, b.a0.w));
        sts64(base + a_sts + 32 * (AH * 2),
              pack_h2(b.a1.x, b.a1.y), pack_h2(b.a1.z, b.a1.w));
        sts64(base + b_sts,
              pack_h2(b.b0.x, b.b0.y), pack_h2(b.b0.z, b.b0.w));
        sts64(base + b_sts + 8 * (BH * 2),
              pack_h2(b.b1.x, b.b1.y), pack_h2(b.b1.z, b.b1.w));
        sts64(base + b_sts + 16 * (BH * 2),
              pack_h2(b.b2.x, b.b2.y), pack_h2(b.b2.z, b.b2.w));
        sts64(base + b_sts + 24 * (BH * 2),
              pack_h2(b.b3.x, b.b3.y), pack_h2(b.b3.z, b.b3.w));
    };
    auto compute = [&](int s) {
        const uint32_t base = sb + s * STG_B;
        const uint32_t aa = base + a_off;
        const uint32_t bb = base + b_off;
#pragma unroll
        for (int kh = 0; kh < 2; ++kh) {
            uint32_t A0[4], A1[4], B0[4], B1[4];
            ldmx4(A0, aa + kh * 32);
            ldmx4(A1, aa + 1280 + kh * 32);      // +16 rows * 80B
            ldmx4t(B0, bb + kh * 4352);          // +16 k-rows * 272B
            ldmx4t(B1, bb + 32 + kh * 4352);     // +16 n

            mma_f16(acc[0][0], A0, &B0[0]);
            mma_f16(acc[0][1], A0, &B0[2]);
            mma_f16(acc[0][2], A0, &B1[0]);
            mma_f16(acc[0][3], A0, &B1[2]);
            mma_f16(acc[1][0], A1, &B0[0]);
            mma_f16(acc[1][1], A1, &B0[2]);
            mma_f16(acc[1][2], A1, &B1[0]);
            mma_f16(acc[1][3], A1, &B1[2]);
        }
    };

    // prologue: stages 0,1 filled; chunks 2,3 resident in bA,bB
    ldg_chunk(bA, 0); cvt_sts(0, bA);
    ldg_chunk(bB, 1); cvt_sts(1, bB);
    ldg_chunk(bA, 2);
    ldg_chunk(bB, 3);

#pragma unroll 1
    for (int t = 0; t < NST; t += 2) {
        // even sub-iteration
        __syncthreads();
        if (t + 2 < NST) cvt_sts((t + 2) & 3, bA);   // chunk t+2 -> ring
        if (t + 4 < NST) ldg_chunk(bA, t + 4);       // consumed at iter t+2
        compute(t & 3);

        // odd sub-iteration
        __syncthreads();
        if (t + 3 < NST) cvt_sts((t + 3) & 3, bB);
        if (t + 5 < NST) ldg_chunk(bB, t + 5);
        compute((t + 1) & 3);
    }

    // ---- epilogue: bias + relu (verified) ----
#pragma unroll
    for (int nt = 0; nt < 4; ++nt) {
        const int n0 = wn * 32 + nt * 8 + t4 * 2;
        const float2 bv = *reinterpret_cast<const float2*>(bias + n0);
#pragma unroll
        for (int mt = 0; mt < 2; ++mt) {
            const int m = wm * 32 + mt * 16 + g;
            float2 o0, o1;
            o0.x = fmaxf(acc[mt][nt][0] + bv.x, 0.f);
            o0.y = fmaxf(acc[mt][nt][1] + bv.y, 0.f);
            o1.x = fmaxf(acc[mt][nt][2] + bv.x, 0.f);
            o1.y = fmaxf(acc[mt][nt][3] + bv.y, 0.f);
            *reinterpret_cast<float2*>(out + ((size_t)m * 256 + l) * 128 + n0) = o0;
            *reinterpret_cast<float2*>(out + ((size_t)(m + 8) * 256 + l) * 128 + n0) = o1;
        }
    }
}

}  // namespace

extern "C" void kernel_launch(void* const* d_in, const int* in_sizes, int n_in,
                              void* d_out, int out_size) {
    const float* X    = (const float*)d_in[0];
    const float* filt = (const float*)d_in[1];
    const float* bias = (const float*)d_in[2];
    float* out        = (float*)d_out;

    cudaFuncSetAttribute(bioconv_d2s_kernel,
                         cudaFuncAttributeMaxDynamicSharedMemorySize, SMEM_BYTES);
    bioconv_d2s_kernel<<<256, 256, SMEM_BYTES>>>(X, filt, bias, out);
}